// round 4
// baseline (speedup 1.0000x reference)
#include <cuda_runtime.h>
#include <math.h>

// BandPass biquad, 128 rows x 200000 samples.  (R3 resubmit of R2 after two
// broker-side container failures; kernel audited clean for bounds/alignment.)
//
// Chunked-parallel IIR: poles at radius ~0.831 => zero-state warmup of W
// samples converges the filter state to ~0.831^W relative error.
// vs R1 (79.8us, DRAM 32.8%, occ 16%): CHUNK_L 500->200 (2.5x threads),
// W 128->64 (residual ~7e-6), grouped float4 preloads (MLP~5/thread),
// streaming cache hints (read-once / write-once data).

#define B_ROWS   128
#define T_LEN    200000
#define CHUNK_L  200          // 200000 / 200 = 1000 chunks per row
#define WARM_W   64           // warmup samples (multiple of 4)
#define N_CHUNKS (T_LEN / CHUNK_L)

// y[n] = b0*x[n] + b2*x[n-2] - a1*y[n-1] - a2*y[n-2]   (b1 == 0 exactly)
#define BQ_STEP(XN, OUT_EXPR)                                               \
    do {                                                                    \
        float xn_ = (XN);                                                   \
        float yn_ = fmaf(b0, xn_, fmaf(b2, x2, fmaf(na1, y1, na2 * y2)));   \
        x2 = x1; x1 = xn_; y2 = y1; y1 = yn_;                               \
        OUT_EXPR;                                                           \
    } while (0)

__global__ __launch_bounds__(128)
void biquad_chunk_kernel(const float* __restrict__ x,
                         float* __restrict__ y,
                         float b0, float b2, float na1, float na2)
{
    int gid = blockIdx.x * blockDim.x + threadIdx.x;
    int row = gid / N_CHUNKS;
    int c   = gid - row * N_CHUNKS;
    if (row >= B_ROWS) return;

    const float* xr = x + (size_t)row * T_LEN;
    float*       yr = y + (size_t)row * T_LEN;
    int s0 = c * CHUNK_L;

    float x1 = 0.0f, x2 = 0.0f, y1 = 0.0f, y2 = 0.0f;

    if (c > 0) {
        // Warmup [s0-W, s0): 64 samples = 16 float4, 4 independent loads per
        // group. These bytes are re-read by the neighboring chunk's main loop,
        // so use default (caching) loads here.
        const float4* wp = (const float4*)(xr + s0 - WARM_W);
#pragma unroll
        for (int g = 0; g < WARM_W / 16; ++g) {
            float4 v0 = wp[g * 4 + 0];
            float4 v1 = wp[g * 4 + 1];
            float4 v2 = wp[g * 4 + 2];
            float4 v3 = wp[g * 4 + 3];
            BQ_STEP(v0.x, ); BQ_STEP(v0.y, ); BQ_STEP(v0.z, ); BQ_STEP(v0.w, );
            BQ_STEP(v1.x, ); BQ_STEP(v1.y, ); BQ_STEP(v1.z, ); BQ_STEP(v1.w, );
            BQ_STEP(v2.x, ); BQ_STEP(v2.y, ); BQ_STEP(v2.z, ); BQ_STEP(v2.w, );
            BQ_STEP(v3.x, ); BQ_STEP(v3.y, ); BQ_STEP(v3.z, ); BQ_STEP(v3.w, );
        }
    }

    // Main chunk: 200 samples = 50 float4, 10 groups of 5 independent
    // streaming loads (MLP~5).  Output is write-once -> streaming stores.
    const float4* xp = (const float4*)(xr + s0);
    float4*       yp = (float4*)(yr + s0);
#pragma unroll 2
    for (int g = 0; g < CHUNK_L / 20; ++g) {
        float4 v0 = __ldcs(xp + g * 5 + 0);
        float4 v1 = __ldcs(xp + g * 5 + 1);
        float4 v2 = __ldcs(xp + g * 5 + 2);
        float4 v3 = __ldcs(xp + g * 5 + 3);
        float4 v4 = __ldcs(xp + g * 5 + 4);
        float4 o0, o1, o2, o3, o4;
        BQ_STEP(v0.x, o0.x = yn_); BQ_STEP(v0.y, o0.y = yn_);
        BQ_STEP(v0.z, o0.z = yn_); BQ_STEP(v0.w, o0.w = yn_);
        BQ_STEP(v1.x, o1.x = yn_); BQ_STEP(v1.y, o1.y = yn_);
        BQ_STEP(v1.z, o1.z = yn_); BQ_STEP(v1.w, o1.w = yn_);
        BQ_STEP(v2.x, o2.x = yn_); BQ_STEP(v2.y, o2.y = yn_);
        BQ_STEP(v2.z, o2.z = yn_); BQ_STEP(v2.w, o2.w = yn_);
        BQ_STEP(v3.x, o3.x = yn_); BQ_STEP(v3.y, o3.y = yn_);
        BQ_STEP(v3.z, o3.z = yn_); BQ_STEP(v3.w, o3.w = yn_);
        BQ_STEP(v4.x, o4.x = yn_); BQ_STEP(v4.y, o4.y = yn_);
        BQ_STEP(v4.z, o4.z = yn_); BQ_STEP(v4.w, o4.w = yn_);
        __stcs(yp + g * 5 + 0, o0);
        __stcs(yp + g * 5 + 1, o1);
        __stcs(yp + g * 5 + 2, o2);
        __stcs(yp + g * 5 + 3, o3);
        __stcs(yp + g * 5 + 4, o4);
    }
}

extern "C" void kernel_launch(void* const* d_in, const int* in_sizes, int n_in,
                              void* d_out, int out_size)
{
    const float* x = (const float*)d_in[0];
    float*       y = (float*)d_out;

    // Coefficients in double, cast to float — mirrors the reference.
    const double SR = 48000.0, CF = 2000.0, Q = 0.707;
    double w0    = 2.0 * M_PI * CF / SR;
    double alpha = sin(w0) / (2.0 * Q);
    double a0    = 1.0 + alpha;
    float b0  = (float)( alpha / a0);
    float b2  = (float)(-alpha / a0);
    float na1 = -(float)((-2.0 * cos(w0)) / a0);
    float na2 = -(float)((1.0 - alpha) / a0);

    int total   = B_ROWS * N_CHUNKS;               // 128000 threads
    int threads = 128;
    int blocks  = (total + threads - 1) / threads; // 1000 blocks
    biquad_chunk_kernel<<<blocks, threads>>>(x, y, b0, b2, na1, na2);
}

// round 5
// speedup vs baseline: 1.9538x; 1.9538x over previous
#include <cuda_runtime.h>
#include <math.h>

// BandPass biquad, 128 rows x 200000 samples.
// R4 post-mortem: both prior kernels were L1tex-WAVEFRONT bound, not DRAM
// bound — per-thread 800B-strided chunks make every warp LDG.128/STG.128
// touch 32 distinct 128B lines (32 wavefronts/inst). Occupancy changes were
// invariant to this, matching R1 (76us @ occ16%) == R4 (84us @ occ37%).
// Fix: warp-cooperative tile transpose through smem so every global access
// is coalesced (4 wavefronts/inst, 128B-aligned segments).
//
// CHUNK_L = 320 floats = 1280B (128B-aligned chunk starts), 625 chunks/row.
// Warp owns 32 consecutive chunks; tiles of 32 samples; warmup 64 samples
// (state residual 0.831^64 ~ 7e-6; chunk 0 warms on zeros == exact init).

#define B_ROWS   128
#define T_LEN    200000
#define CHUNK_L  320
#define NCH      625          // chunks per row  (625*320 = 200000)
#define TS       32           // samples per tile
#define NF4      8            // float4 per chunk per tile
#define W_TILES  2            // warmup tiles = 64 samples
#define N_TILES  (CHUNK_L / TS)   // 10
#define PAD      33           // smem row pad (float4 units) -> conflict-free

// y[n] = b0*x[n] + b2*x[n-2] - a1*y[n-1] - a2*y[n-2]   (b1 == 0 exactly)
#define BQ_STEP(XN, OUT_EXPR)                                               \
    do {                                                                    \
        float xn_ = (XN);                                                   \
        float yn_ = fmaf(b0, xn_, fmaf(b2, x2, fmaf(na1, y1, na2 * y2)));   \
        x2 = x1; x1 = xn_; y2 = y1; y1 = yn_;                               \
        OUT_EXPR;                                                           \
    } while (0)

__global__ __launch_bounds__(128)
void biquad_coal_kernel(const float* __restrict__ x,
                        float* __restrict__ y,
                        float b0, float b2, float na1, float na2)
{
    // one tile buffer per warp: [f4-row][segment], padded
    __shared__ float4 buf[4][NF4][PAD];

    const int wid   = threadIdx.x >> 5;
    const int lane  = threadIdx.x & 31;
    const int warpG = blockIdx.x * 4 + wid;      // 0..2499

    // load/store role: lane covers (seg = 4i + sL, f4 = fL)
    const int fL = lane & 7;
    const int sL = lane >> 3;

    // Precompute the 8 gmem base pointers (one per load instruction) and the
    // "is chunk 0 of its row" flag. seg/row/chunk are t-invariant.
    const float* px[8];
    float*       py[8];
    int          isC0[8];
#pragma unroll
    for (int i = 0; i < 8; ++i) {
        int g   = warpG * 32 + i * 4 + sL;       // global chunk id
        int row = g / NCH;
        int c   = g - row * NCH;
        size_t off = (size_t)row * T_LEN + (size_t)c * CHUNK_L + fL * 4;
        px[i]   = x + off;
        py[i]   = y + off;
        isC0[i] = (c == 0);
    }

    float4 (*tb)[PAD] = buf[wid];

    float x1 = 0.0f, x2 = 0.0f, y1 = 0.0f, y2 = 0.0f;

    for (int t = -W_TILES; t < N_TILES; ++t) {
        const int toff = t * TS;

        // ---- phase 1: coalesced gmem loads (8 x LDG.128, 4 aligned
        //      128B segments each = 4 wavefronts/inst)
        float4 r[8];
#pragma unroll
        for (int i = 0; i < 8; ++i) {
            if (isC0[i] && t < 0)
                r[i] = make_float4(0.0f, 0.0f, 0.0f, 0.0f);  // zero-state warmup
            else
                r[i] = *(const float4*)(px[i] + toff);
        }
        __syncwarp();
        // ---- phase 2: transpose into smem
#pragma unroll
        for (int i = 0; i < 8; ++i)
            tb[fL][i * 4 + sL] = r[i];
        __syncwarp();

        // ---- phase 3: each lane runs 32 recurrence steps on its own chunk
        float4 o[8];
#pragma unroll
        for (int f = 0; f < 8; ++f) {
            float4 v = tb[f][lane];
            float4 oo;
            BQ_STEP(v.x, oo.x = yn_);
            BQ_STEP(v.y, oo.y = yn_);
            BQ_STEP(v.z, oo.z = yn_);
            BQ_STEP(v.w, oo.w = yn_);
            o[f] = oo;
        }
        __syncwarp();

        if (t >= 0) {
            // ---- phase 4: outputs through smem, coalesced STG
#pragma unroll
            for (int f = 0; f < 8; ++f)
                tb[f][lane] = o[f];
            __syncwarp();
#pragma unroll
            for (int i = 0; i < 8; ++i)
                *(float4*)(py[i] + toff) = tb[fL][i * 4 + sL];
            __syncwarp();
        }
    }
}

extern "C" void kernel_launch(void* const* d_in, const int* in_sizes, int n_in,
                              void* d_out, int out_size)
{
    const float* x = (const float*)d_in[0];
    float*       y = (float*)d_out;

    // Coefficients in double, cast to float — mirrors the reference.
    const double SR = 48000.0, CF = 2000.0, Q = 0.707;
    double w0    = 2.0 * M_PI * CF / SR;
    double alpha = sin(w0) / (2.0 * Q);
    double a0    = 1.0 + alpha;
    float b0  = (float)( alpha / a0);
    float b2  = (float)(-alpha / a0);
    float na1 = -(float)((-2.0 * cos(w0)) / a0);
    float na2 = -(float)((1.0 - alpha) / a0);

    // 128 rows * 625 chunks = 80000 threads = 2500 warps; 4 warps/block
    int blocks = (B_ROWS * NCH) / 128;   // 625
    biquad_coal_kernel<<<blocks, 128>>>(x, y, b0, b2, na1, na2);
}